// round 13
// baseline (speedup 1.0000x reference)
#include <cuda_runtime.h>
#include <cuda_fp16.h>

#define NA 300000
#define NT 300000
#define HID 32
#define NH 4
#define E_IN 1000000
#define E_OUT 1000000
#define E_SP 500000
#define E_TOT (E_IN + E_OUT + E_SP)
#define NLAYERS 4
#define SCAN_B 1024

// ---------------- device scratch (no allocs allowed) ----------------
__device__ float  g_xa[NA * HID];
__device__ float  g_xt[NT * HID];
__device__ __half g_ha[NA * HID];          // fp16 message payload
__device__ __half g_ht[NT * HID];
__device__ float  g_asrc0[NA * NH];
__device__ float  g_adst0[NT * NH];
__device__ float  g_asrc1[NT * NH];
__device__ float  g_adst1[NA * NH];
__device__ float  g_asrc2[NT * NH];
__device__ float  g_adst2[NT * NH];
__device__ float  g_o0[NT * HID];
__device__ float  g_o2[NT * HID];
__device__ float  g_sacc[2 * 32 * 32];     // padded: lane j at [j*32]
__device__ float  g_attn[2];
// CSR scratch
__device__ int g_rp0[NT + 1];
__device__ int g_rp1[NA + 1];
__device__ int g_rp2[NT + 1];
__device__ int g_wcur0[NT];
__device__ int g_wcur1[NA];
__device__ int g_wcur2[NT];
__device__ int g_adj0[E_IN];
__device__ int g_adj1[E_OUT];
__device__ int g_adj2[E_SP];
__device__ int g_bsums0[SCAN_B];
__device__ int g_bsums1[SCAN_B];
__device__ int g_bsums2[SCAN_B];

// ---------------- helpers ----------------
__device__ __forceinline__ float wsum32(float v) {
    #pragma unroll
    for (int o = 16; o > 0; o >>= 1) v += __shfl_xor_sync(0xffffffffu, v, o);
    return v;
}

// ---------------- CSR build ----------------
// one kernel zeroes all six CSR arrays (replaces 6 memsets)
__global__ void zero_csr(int* __restrict__ rp0, int* __restrict__ rp1, int* __restrict__ rp2,
                         int* __restrict__ wc0, int* __restrict__ wc1, int* __restrict__ wc2) {
    int t = blockIdx.x * blockDim.x + threadIdx.x;
    const int nA = NT + 1, nB = NA + 1, nC = NT + 1;
    if (t < nA) rp0[t] = 0;
    else if (t < nA + nB) rp1[t - nA] = 0;
    else if (t < nA + nB + nC) rp2[t - nA - nB] = 0;
    else {
        int u = t - nA - nB - nC;
        if (u < NT) wc0[u] = 0;
        else if (u < NT + NA) wc1[u - NT] = 0;
        else if (u < NT + NA + NT) wc2[u - NT - NA] = 0;
    }
}

__global__ void count_all(const int* __restrict__ ei0, const int* __restrict__ ei1,
                          const int* __restrict__ ei2,
                          int* __restrict__ d0, int* __restrict__ d1, int* __restrict__ d2) {
    int t = blockIdx.x * blockDim.x + threadIdx.x;
    if (t < E_IN)                  atomicAdd(&d0[__ldg(ei0 + E_IN + t)], 1);
    else if (t < E_IN + E_OUT)     atomicAdd(&d1[__ldg(ei1 + E_OUT + (t - E_IN))], 1);
    else if (t < E_TOT)            atomicAdd(&d2[__ldg(ei2 + E_SP + (t - E_IN - E_OUT))], 1);
}

// fused per-block scan of all three degree arrays
__global__ void scan1_all(int* __restrict__ d0, int* __restrict__ b0, int n0, int nb0,
                          int* __restrict__ d1, int* __restrict__ b1, int n1, int nb1,
                          int* __restrict__ d2, int* __restrict__ b2, int n2) {
    int* d; int* bs; int n; int lb;
    if (blockIdx.x < nb0)            { d = d0; bs = b0; n = n0; lb = blockIdx.x; }
    else if (blockIdx.x < nb0 + nb1) { d = d1; bs = b1; n = n1; lb = blockIdx.x - nb0; }
    else                             { d = d2; bs = b2; n = n2; lb = blockIdx.x - nb0 - nb1; }
    __shared__ int s[SCAN_B];
    int i = lb * SCAN_B + threadIdx.x;
    int v = (i < n) ? d[i] : 0;
    s[threadIdx.x] = v;
    __syncthreads();
    for (int o = 1; o < SCAN_B; o <<= 1) {
        int t = (threadIdx.x >= o) ? s[threadIdx.x - o] : 0;
        __syncthreads();
        s[threadIdx.x] += t;
        __syncthreads();
    }
    if (i < n) d[i] = s[threadIdx.x] - v;        // exclusive
    if (threadIdx.x == SCAN_B - 1) bs[lb] = s[SCAN_B - 1];
}

// fused block-sum scan: 3 blocks, one per bsums array
__global__ void scan2_all(int* __restrict__ b0, int nb0,
                          int* __restrict__ b1, int nb1,
                          int* __restrict__ b2, int nb2) {
    int* bs; int nb;
    if (blockIdx.x == 0)      { bs = b0; nb = nb0; }
    else if (blockIdx.x == 1) { bs = b1; nb = nb1; }
    else                      { bs = b2; nb = nb2; }
    __shared__ int s[SCAN_B];
    int v = (threadIdx.x < nb) ? bs[threadIdx.x] : 0;
    s[threadIdx.x] = v;
    __syncthreads();
    for (int o = 1; o < SCAN_B; o <<= 1) {
        int t = (threadIdx.x >= o) ? s[threadIdx.x - o] : 0;
        __syncthreads();
        s[threadIdx.x] += t;
        __syncthreads();
    }
    if (threadIdx.x < nb) bs[threadIdx.x] = s[threadIdx.x] - v;   // exclusive
}

// fused add-back + terminators
__global__ void scan3_all(int* __restrict__ d0, const int* __restrict__ b0, int n0, int nb0,
                          int* __restrict__ d1, const int* __restrict__ b1, int n1, int nb1,
                          int* __restrict__ d2, const int* __restrict__ b2, int n2) {
    if (blockIdx.x == 0 && threadIdx.x == 0) {
        d0[n0] = E_IN; d1[n1] = E_OUT; d2[n2] = E_SP;
    }
    int* d; const int* bs; int n; int lb;
    if (blockIdx.x < nb0)            { d = d0; bs = b0; n = n0; lb = blockIdx.x; }
    else if (blockIdx.x < nb0 + nb1) { d = d1; bs = b1; n = n1; lb = blockIdx.x - nb0; }
    else                             { d = d2; bs = b2; n = n2; lb = blockIdx.x - nb0 - nb1; }
    int i = lb * SCAN_B + threadIdx.x;
    if (i < n) d[i] += bs[lb];
}

__global__ void fill_all(const int* __restrict__ ei0, const int* __restrict__ ei1,
                         const int* __restrict__ ei2,
                         const int* __restrict__ r0, const int* __restrict__ r1,
                         const int* __restrict__ r2,
                         int* __restrict__ w0, int* __restrict__ w1, int* __restrict__ w2,
                         int* __restrict__ a0, int* __restrict__ a1, int* __restrict__ a2) {
    int t = blockIdx.x * blockDim.x + threadIdx.x;
    const int* ei; const int* r; int* w; int* adj; int e, E;
    if (t < E_IN)              { ei = ei0; r = r0; w = w0; adj = a0; e = t;                 E = E_IN;  }
    else if (t < E_IN + E_OUT) { ei = ei1; r = r1; w = w1; adj = a1; e = t - E_IN;          E = E_OUT; }
    else if (t < E_TOT)        { ei = ei2; r = r2; w = w2; adj = a2; e = t - E_IN - E_OUT;  E = E_SP;  }
    else return;
    int si = __ldg(ei + e);
    int di = __ldg(ei + E + e);
    int pos = r[di] + atomicAdd(&w[di], 1);
    adj[pos] = si;
}

// ---------------- node kernels ----------------
__global__ void enc_kernel(const float* __restrict__ x, const float* __restrict__ W,
                           const float* __restrict__ b, float* __restrict__ out,
                           int n, int K) {
    extern __shared__ float Ws[];
    for (int i = threadIdx.x; i < K * 32; i += blockDim.x) Ws[i] = W[i];
    __syncthreads();
    int lane = threadIdx.x & 31;
    int warp = blockIdx.x * (blockDim.x >> 5) + (threadIdx.x >> 5);
    int nw = gridDim.x * (blockDim.x >> 5);
    float bl = b[lane];
    for (int node = warp; node < n; node += nw) {
        const float* xr = x + (size_t)node * K;
        float acc = bl;
        for (int k = 0; k < K; k++) acc = fmaf(xr[k], Ws[k * 32 + lane], acc);
        out[node * 32 + lane] = fmaxf(acc, 0.f);
    }
}

// tiled projection with 4-node register reuse: tile = 128 nodes, thread owns
// a 4-column quad for 4 nodes, so each Ws float4 load feeds 16 FMAs.
// STOREH=false skips the fp16 h store (used when h is dead in the last layer).
template <int NATT, bool STOREH>
__global__ void projT_kernel(const float* __restrict__ x, const float* __restrict__ W,
                             const float* __restrict__ b, __half* __restrict__ hout, int n,
                             const float* __restrict__ a0, float* __restrict__ o0,
                             const float* __restrict__ a1, float* __restrict__ o1,
                             const float* __restrict__ a2, float* __restrict__ o2,
                             const float* __restrict__ a3, float* __restrict__ o3) {
    __shared__ float Ws[32 * 32];
    __shared__ float Xs[128 * 33];
    int tid = threadIdx.x;
    for (int i = tid; i < 1024; i += blockDim.x) Ws[i] = W[i];
    int nl = tid >> 3;            // node-slot within 32 (0..31)
    int jq = (tid & 7) * 4;       // first output column of this thread's quad
    int head = (tid & 7) >> 1;    // head covered by this quad-pair
    float4 bq = *(const float4*)(b + jq);
    float4 av0 = make_float4(0,0,0,0), av1 = av0, av2 = av0, av3 = av0;
    if (NATT > 0) av0 = *(const float4*)(a0 + jq);
    if (NATT > 1) av1 = *(const float4*)(a1 + jq);
    if (NATT > 2) av2 = *(const float4*)(a2 + jq);
    if (NATT > 3) av3 = *(const float4*)(a3 + jq);
    __syncthreads();
    int ntiles = (n + 127) >> 7;
    for (int tile = blockIdx.x; tile < ntiles; tile += gridDim.x) {
        int base = tile * 128;
        #pragma unroll
        for (int r = 0; r < 4; r++) {
            int node = base + nl + r * 32;
            float4 xq = (node < n) ? *(const float4*)(x + (size_t)node * 32 + jq)
                                   : make_float4(0.f, 0.f, 0.f, 0.f);
            int row = nl + r * 32;
            Xs[row * 33 + jq + 0] = xq.x;
            Xs[row * 33 + jq + 1] = xq.y;
            Xs[row * 33 + jq + 2] = xq.z;
            Xs[row * 33 + jq + 3] = xq.w;
        }
        __syncthreads();
        float4 acc[4] = {bq, bq, bq, bq};
        #pragma unroll
        for (int k = 0; k < 32; k++) {
            float4 wk = *(const float4*)(Ws + k * 32 + jq);
            #pragma unroll
            for (int r = 0; r < 4; r++) {
                float xk = Xs[(nl + r * 32) * 33 + k];
                acc[r].x = fmaf(xk, wk.x, acc[r].x);
                acc[r].y = fmaf(xk, wk.y, acc[r].y);
                acc[r].z = fmaf(xk, wk.z, acc[r].z);
                acc[r].w = fmaf(xk, wk.w, acc[r].w);
            }
        }
        #pragma unroll
        for (int r = 0; r < 4; r++) {
            int node = base + nl + r * 32;
            bool valid = node < n;
            if (STOREH && valid) {
                __half2 p0 = __floats2half2_rn(acc[r].x, acc[r].y);
                __half2 p1 = __floats2half2_rn(acc[r].z, acc[r].w);
                __half2* hp = (__half2*)(hout + (size_t)node * 32 + jq);
                hp[0] = p0;
                hp[1] = p1;
            }
            #define DOTQ(av, ov) { \
                float p = acc[r].x*(av).x + acc[r].y*(av).y + acc[r].z*(av).z + acc[r].w*(av).w; \
                p += __shfl_xor_sync(0xffffffffu, p, 1); \
                if (valid && ((tid & 1) == 0)) (ov)[node * 4 + head] = p; }
            if (NATT > 0) DOTQ(av0, o0)
            if (NATT > 1) DOTQ(av1, o1)
            if (NATT > 2) DOTQ(av2, o2)
            if (NATT > 3) DOTQ(av3, o3)
            #undef DOTQ
        }
        __syncthreads();
    }
}

// ---------------- fused gather-aggregation ----------------
#define EDGE(AS, H, AD, DEN, ACC)                                       \
    {                                                                   \
        float _v = (AS) + (AD);                                         \
        if (_v < 0.f) _v *= 0.2f;                                       \
        float _e = __expf(_v);                                          \
        (DEN) += _e;                                                    \
        (ACC) = fmaf(_e, (H), (ACC));                                   \
    }

// single-relation gather, unroll x4; h payload in fp16 (64B/warp/edge)
__device__ __forceinline__ float gather_rel(const int* __restrict__ rp,
                                            const int* __restrict__ adj,
                                            const float* __restrict__ asrc,
                                            const float* __restrict__ adst,
                                            const __half* __restrict__ h,
                                            int node, int lane, int hoff) {
    float ad = __ldg(adst + node * 4 + hoff);
    int s = __ldg(rp + node), e = __ldg(rp + node + 1);
    float den = 0.f, acc = 0.f;
    int i = s;
    for (; i + 4 <= e; i += 4) {
        int a = __ldg(adj + i),     b = __ldg(adj + i + 1);
        int c = __ldg(adj + i + 2), d = __ldg(adj + i + 3);
        float sa = __ldg(asrc + a * 4 + hoff), sb = __ldg(asrc + b * 4 + hoff);
        float sc = __ldg(asrc + c * 4 + hoff), sd = __ldg(asrc + d * 4 + hoff);
        float hA = __half2float(__ldg(h + (size_t)a * 32 + lane));
        float hB = __half2float(__ldg(h + (size_t)b * 32 + lane));
        float hC = __half2float(__ldg(h + (size_t)c * 32 + lane));
        float hD = __half2float(__ldg(h + (size_t)d * 32 + lane));
        EDGE(sa, hA, ad, den, acc)
        EDGE(sb, hB, ad, den, acc)
        EDGE(sc, hC, ad, den, acc)
        EDGE(sd, hD, ad, den, acc)
    }
    if (i + 2 <= e) {
        int a = __ldg(adj + i), b = __ldg(adj + i + 1);
        float sa = __ldg(asrc + a * 4 + hoff), sb = __ldg(asrc + b * 4 + hoff);
        float hA = __half2float(__ldg(h + (size_t)a * 32 + lane));
        float hB = __half2float(__ldg(h + (size_t)b * 32 + lane));
        EDGE(sa, hA, ad, den, acc)
        EDGE(sb, hB, ad, den, acc)
        i += 2;
    }
    if (i < e) {
        int a = __ldg(adj + i);
        float sa = __ldg(asrc + a * 4 + hoff);
        float hA = __half2float(__ldg(h + (size_t)a * 32 + lane));
        EDGE(sa, hA, ad, den, acc)
    }
    return fmaxf(acc * (1.f / (den + 1e-16f)), 0.f);
}

// agg with the semantic-score GEMV fused in (x0/x2 scored while in registers)
__global__ void agg_kernel(const int* __restrict__ rp0, const int* __restrict__ adj0,
                           const int* __restrict__ rp2, const int* __restrict__ adj2,
                           const int* __restrict__ rp1, const int* __restrict__ adj1,
                           const float* __restrict__ asrc0, const float* __restrict__ adst0,
                           const float* __restrict__ asrc2, const float* __restrict__ adst2,
                           const float* __restrict__ asrc1, const float* __restrict__ adst1,
                           const __half* __restrict__ ha, const __half* __restrict__ ht,
                           float* __restrict__ o0out, float* __restrict__ o2out,
                           float* __restrict__ xa,
                           const float* __restrict__ lng, const float* __restrict__ lnb,
                           const float* __restrict__ kw, const float* __restrict__ kb,
                           float* __restrict__ sacc) {
    __shared__ float KWs[32 * 32];
    __shared__ float s0[32], s2[32];
    for (int i = threadIdx.x; i < 1024; i += blockDim.x) KWs[i] = kw[i];
    if (threadIdx.x < 32) { s0[threadIdx.x] = 0.f; s2[threadIdx.x] = 0.f; }
    __syncthreads();
    int lane = threadIdx.x & 31;
    int warp = blockIdx.x * (blockDim.x >> 5) + (threadIdx.x >> 5);
    int nw = gridDim.x * (blockDim.x >> 5);
    int hoff = lane >> 3;
    float gl = lng[lane], bl = lnb[lane];
    float kbl = kb[lane];
    float t0 = 0.f, t2 = 0.f;
    for (int idx = warp; idx < NT + NA; idx += nw) {
        if (idx < NT) {
            int node = idx;
            float x0 = gather_rel(rp0, adj0, asrc0, adst0, ha, node, lane, hoff);
            float x2 = gather_rel(rp2, adj2, asrc2, adst2, ht, node, lane, hoff);
            o0out[(size_t)node * 32 + lane] = x0;
            o2out[(size_t)node * 32 + lane] = x2;
            // fused semantic-score GEMV: a = x @ kw + kb, accumulate tanh(a)
            float a0 = kbl, a2 = kbl;
            #pragma unroll
            for (int k = 0; k < 32; k++) {
                float w = KWs[k * 32 + lane];
                a0 = fmaf(__shfl_sync(0xffffffffu, x0, k), w, a0);
                a2 = fmaf(__shfl_sync(0xffffffffu, x2, k), w, a2);
            }
            t0 += tanhf(a0);
            t2 += tanhf(a2);
        } else {
            int node = idx - NT;
            float o = gather_rel(rp1, adj1, asrc1, adst1, ht, node, lane, hoff);
            int i = node * 32 + lane;
            float v = o + xa[i];        // relation-group softmax weight is exactly 1
            float m = wsum32(v) * (1.f / 32.f);
            float c = v - m;
            float var = wsum32(c * c) * (1.f / 32.f);
            xa[i] = c * rsqrtf(var + 1e-5f) * gl + bl;
        }
    }
    __syncthreads();
    atomicAdd(&s0[lane], t0);
    atomicAdd(&s2[lane], t2);
    __syncthreads();
    if (threadIdx.x < 32) {
        atomicAdd(&sacc[threadIdx.x * 32], s0[threadIdx.x]);
        atomicAdd(&sacc[1024 + threadIdx.x * 32], s2[threadIdx.x]);
    }
}

// addr-only aggregation for the last layer (tx path is dead code)
__global__ void agg_addr_kernel(const int* __restrict__ rp1, const int* __restrict__ adj1,
                                const float* __restrict__ asrc1, const float* __restrict__ adst1,
                                const __half* __restrict__ ht, float* __restrict__ xa,
                                const float* __restrict__ lng, const float* __restrict__ lnb) {
    int lane = threadIdx.x & 31;
    int warp = blockIdx.x * (blockDim.x >> 5) + (threadIdx.x >> 5);
    int nw = gridDim.x * (blockDim.x >> 5);
    int hoff = lane >> 3;
    float gl = lng[lane], bl = lnb[lane];
    for (int node = warp; node < NA; node += nw) {
        float o = gather_rel(rp1, adj1, asrc1, adst1, ht, node, lane, hoff);
        int i = node * 32 + lane;
        float v = o + xa[i];
        float m = wsum32(v) * (1.f / 32.f);
        float c = v - m;
        float var = wsum32(c * c) * (1.f / 32.f);
        xa[i] = c * rsqrtf(var + 1e-5f) * gl + bl;
    }
}

// softmax over the 2 tx-relation scores
__global__ void score_fin(const float* __restrict__ acc0, const float* __restrict__ acc2,
                          const float* __restrict__ q, float* __restrict__ attn, float invN) {
    int j = threadIdx.x;  // 32 threads
    float s0 = q[j] * acc0[j * 32] * invN;
    float s2 = q[j] * acc2[j * 32] * invN;
    s0 = wsum32(s0);
    s2 = wsum32(s2);
    if (j == 0) {
        float m = fmaxf(s0, s2);
        float e0 = __expf(s0 - m), e2 = __expf(s2 - m);
        float inv = 1.f / (e0 + e2);
        attn[0] = e0 * inv;
        attn[1] = e2 * inv;
    }
}

__global__ void upd_tx_kernel(const float* __restrict__ o0, const float* __restrict__ o2,
                              const float* __restrict__ attn, float* __restrict__ xt,
                              const float* __restrict__ g, const float* __restrict__ b, int n) {
    int lane = threadIdx.x & 31;
    int node = blockIdx.x * (blockDim.x >> 5) + (threadIdx.x >> 5);
    if (node >= n) return;
    float a0 = attn[0], a2 = attn[1];
    int i = node * 32 + lane;
    float v = fmaxf(a0 * o0[i] + a2 * o2[i], 0.f) + xt[i];
    float m = wsum32(v) * (1.f / 32.f);
    float c = v - m;
    float var = wsum32(c * c) * (1.f / 32.f);
    xt[i] = c * rsqrtf(var + 1e-5f) * g[lane] + b[lane];
}

__global__ void head_kernel(const float* __restrict__ xa, const float* __restrict__ w,
                            const float* __restrict__ b, float* __restrict__ out, int n) {
    int lane = threadIdx.x & 31;
    int node = blockIdx.x * (blockDim.x >> 5) + (threadIdx.x >> 5);
    if (node >= n) return;
    float v = xa[node * 32 + lane];
    float s0 = wsum32(v * w[lane * 2 + 0]);
    float s1 = wsum32(v * w[lane * 2 + 1]);
    if (lane == 0) {
        out[node * 2 + 0] = s0 + b[0];
        out[node * 2 + 1] = s1 + b[1];
    }
}

// ---------------- launch ----------------
extern "C" void kernel_launch(void* const* d_in, const int* in_sizes, int n_in,
                              void* d_out, int out_size) {
    const float* x_addr  = (const float*)d_in[0];
    const float* x_tx    = (const float*)d_in[1];
    const int*   ei_in   = (const int*)d_in[2];
    const int*   ei_out  = (const int*)d_in[3];
    const int*   ei_sp   = (const int*)d_in[4];
    const float* enc_w_a = (const float*)d_in[5];
    const float* enc_b_a = (const float*)d_in[6];
    const float* enc_w_t = (const float*)d_in[7];
    const float* enc_b_t = (const float*)d_in[8];
    const float* ln_a_g  = (const float*)d_in[9];
    const float* ln_a_b  = (const float*)d_in[10];
    const float* ln_t_g  = (const float*)d_in[11];
    const float* ln_t_b  = (const float*)d_in[12];
    const float* pw_a    = (const float*)d_in[13];
    const float* pb_a    = (const float*)d_in[14];
    const float* pw_t    = (const float*)d_in[15];
    const float* pb_t    = (const float*)d_in[16];
    const float* att_src = (const float*)d_in[17];
    const float* att_dst = (const float*)d_in[18];
    const float* klin_w  = (const float*)d_in[19];
    const float* klin_b  = (const float*)d_in[20];
    const float* qv      = (const float*)d_in[21];
    const float* lin_w   = (const float*)d_in[22];
    const float* lin_b   = (const float*)d_in[23];
    float* out = (float*)d_out;

    float *xa, *xt;
    __half *ha, *ht;
    float *asrc0, *adst0, *asrc1, *adst1, *asrc2, *adst2;
    float *o0, *o2, *sacc, *attn;
    int *rp0, *rp1, *rp2, *wc0, *wc1, *wc2, *adj0, *adj1, *adj2, *bs0, *bs1, *bs2;
    cudaGetSymbolAddress((void**)&xa, g_xa);
    cudaGetSymbolAddress((void**)&xt, g_xt);
    cudaGetSymbolAddress((void**)&ha, g_ha);
    cudaGetSymbolAddress((void**)&ht, g_ht);
    cudaGetSymbolAddress((void**)&asrc0, g_asrc0);
    cudaGetSymbolAddress((void**)&adst0, g_adst0);
    cudaGetSymbolAddress((void**)&asrc1, g_asrc1);
    cudaGetSymbolAddress((void**)&adst1, g_adst1);
    cudaGetSymbolAddress((void**)&asrc2, g_asrc2);
    cudaGetSymbolAddress((void**)&adst2, g_adst2);
    cudaGetSymbolAddress((void**)&o0, g_o0);
    cudaGetSymbolAddress((void**)&o2, g_o2);
    cudaGetSymbolAddress((void**)&sacc, g_sacc);
    cudaGetSymbolAddress((void**)&attn, g_attn);
    cudaGetSymbolAddress((void**)&rp0, g_rp0);
    cudaGetSymbolAddress((void**)&rp1, g_rp1);
    cudaGetSymbolAddress((void**)&rp2, g_rp2);
    cudaGetSymbolAddress((void**)&wc0, g_wcur0);
    cudaGetSymbolAddress((void**)&wc1, g_wcur1);
    cudaGetSymbolAddress((void**)&wc2, g_wcur2);
    cudaGetSymbolAddress((void**)&adj0, g_adj0);
    cudaGetSymbolAddress((void**)&adj1, g_adj1);
    cudaGetSymbolAddress((void**)&adj2, g_adj2);
    cudaGetSymbolAddress((void**)&bs0, g_bsums0);
    cudaGetSymbolAddress((void**)&bs1, g_bsums1);
    cudaGetSymbolAddress((void**)&bs2, g_bsums2);

    const int WPB = 8;
    const int TPB = WPB * 32;        // 256 threads
    dim3 gridA((NA + WPB - 1) / WPB), gridT((NT + WPB - 1) / WPB), blk(TPB);
    const int PGRID = 1184;          // persistent grid (agg)
    const int TGRID = 1480;          // tiled-GEMM grid (proj)

    // ---- CSR build (graph static across layers) ----
    const int ZTOT = (NT + 1) + (NA + 1) + (NT + 1) + NT + NA + NT;
    zero_csr<<<(ZTOT + 255) / 256, 256>>>(rp0, rp1, rp2, wc0, wc1, wc2);
    count_all<<<(E_TOT + 255) / 256, 256>>>(ei_in, ei_out, ei_sp, rp0, rp1, rp2);
    int nbT = (NT + SCAN_B - 1) / SCAN_B;
    int nbA = (NA + SCAN_B - 1) / SCAN_B;
    scan1_all<<<nbT + nbA + nbT, SCAN_B>>>(rp0, bs0, NT, nbT, rp1, bs1, NA, nbA, rp2, bs2, NT);
    scan2_all<<<3, SCAN_B>>>(bs0, nbT, bs1, nbA, bs2, nbT);
    scan3_all<<<nbT + nbA + nbT, SCAN_B>>>(rp0, bs0, NT, nbT, rp1, bs1, NA, nbA, rp2, bs2, NT);
    fill_all<<<(E_TOT + 255) / 256, 256>>>(ei_in, ei_out, ei_sp, rp0, rp1, rp2,
                                           wc0, wc1, wc2, adj0, adj1, adj2);

    // ---- encoders ----
    enc_kernel<<<TGRID, TPB, 53 * 32 * 4>>>(x_addr, enc_w_a, enc_b_a, xa, NA, 53);
    enc_kernel<<<TGRID, TPB, 6 * 32 * 4>>>(x_tx, enc_w_t, enc_b_t, xt, NT, 6);

    // ---- layers 1..3 (full) ----
    for (int l = 0; l < NLAYERS - 1; l++) {
        const float* PWA = pw_a + l * 32 * 32;
        const float* PBA = pb_a + l * 32;
        const float* PWT = pw_t + l * 32 * 32;
        const float* PBT = pb_t + l * 32;
        const float* AS = att_src + l * 3 * 32;  // [3][32]
        const float* AD = att_dst + l * 3 * 32;
        const float* KW = klin_w + l * 32 * 32;
        const float* KB = klin_b + l * 32;
        const float* Q  = qv + l * 32;

        projT_kernel<2, true><<<TGRID, blk>>>(xa, PWA, PBA, ha, NA,
                                              AS + 0 * 32, asrc0,   // rel0 src = addr
                                              AD + 1 * 32, adst1,   // rel1 dst = addr
                                              nullptr, nullptr, nullptr, nullptr);
        projT_kernel<4, true><<<TGRID, blk>>>(xt, PWT, PBT, ht, NT,
                                              AD + 0 * 32, adst0,   // rel0 dst = tx
                                              AS + 1 * 32, asrc1,   // rel1 src = tx
                                              AS + 2 * 32, asrc2,   // rel2 src = tx
                                              AD + 2 * 32, adst2);

        cudaMemsetAsync(sacc, 0, 2 * 32 * 32 * sizeof(float));

        agg_kernel<<<PGRID, blk>>>(rp0, adj0, rp2, adj2, rp1, adj1,
                                   asrc0, adst0, asrc2, adst2, asrc1, adst1,
                                   ha, ht, o0, o2, xa, ln_a_g, ln_a_b,
                                   KW, KB, sacc);
        score_fin<<<1, 32>>>(sacc, sacc + 1024, Q, attn, 1.0f / (float)NT);
        upd_tx_kernel<<<gridT, blk>>>(o0, o2, attn, xt, ln_t_g, ln_t_b, NT);
    }

    // ---- layer 4: tx output is dead (only xa reaches the head) ----
    {
        const int l = NLAYERS - 1;
        const float* PWA = pw_a + l * 32 * 32;
        const float* PBA = pb_a + l * 32;
        const float* PWT = pw_t + l * 32 * 32;
        const float* PBT = pb_t + l * 32;
        const float* AS = att_src + l * 3 * 32;
        const float* AD = att_dst + l * 3 * 32;

        // addr projection: only adst1 needed, h is dead
        projT_kernel<1, false><<<TGRID, blk>>>(xa, PWA, PBA, ha, NA,
                                               AD + 1 * 32, adst1,
                                               nullptr, nullptr, nullptr, nullptr,
                                               nullptr, nullptr);
        // tx projection: ht + asrc1 needed only
        projT_kernel<1, true><<<TGRID, blk>>>(xt, PWT, PBT, ht, NT,
                                              AS + 1 * 32, asrc1,
                                              nullptr, nullptr, nullptr, nullptr,
                                              nullptr, nullptr);
        agg_addr_kernel<<<PGRID, blk>>>(rp1, adj1, asrc1, adst1, ht, xa, ln_a_g, ln_a_b);
    }

    head_kernel<<<gridA, blk>>>(xa, lin_w, lin_b, out, NA);
}

// round 14
// speedup vs baseline: 1.1422x; 1.1422x over previous
#include <cuda_runtime.h>
#include <cuda_fp16.h>

#define NA 300000
#define NT 300000
#define HID 32
#define NH 4
#define E_IN 1000000
#define E_OUT 1000000
#define E_SP 500000
#define E_TOT (E_IN + E_OUT + E_SP)
#define NLAYERS 4
#define SCAN_B 1024

// ---------------- device scratch (no allocs allowed) ----------------
__device__ float  g_xa[NA * HID];
__device__ float  g_xt[NT * HID];
__device__ __half g_ha[NA * HID];          // fp16 message payload
__device__ __half g_ht[NT * HID];
__device__ float  g_asrc0[NA * NH];
__device__ float  g_adst0[NT * NH];
__device__ float  g_asrc1[NT * NH];
__device__ float  g_adst1[NA * NH];
__device__ float  g_asrc2[NT * NH];
__device__ float  g_adst2[NT * NH];
__device__ float  g_o0[NT * HID];
__device__ float  g_o2[NT * HID];
__device__ float  g_sacc[2 * 32 * 32];     // padded: lane j at [j*32]
__device__ float  g_attn[2];
// CSR scratch
__device__ int g_rp0[NT + 1];
__device__ int g_rp1[NA + 1];
__device__ int g_rp2[NT + 1];
__device__ int g_wcur0[NT];
__device__ int g_wcur1[NA];
__device__ int g_wcur2[NT];
__device__ int g_adj0[E_IN];
__device__ int g_adj1[E_OUT];
__device__ int g_adj2[E_SP];
__device__ int g_bsums0[SCAN_B];
__device__ int g_bsums1[SCAN_B];
__device__ int g_bsums2[SCAN_B];

// ---------------- helpers ----------------
__device__ __forceinline__ float wsum32(float v) {
    #pragma unroll
    for (int o = 16; o > 0; o >>= 1) v += __shfl_xor_sync(0xffffffffu, v, o);
    return v;
}

// ---------------- CSR build ----------------
__global__ void zero_csr(int* __restrict__ rp0, int* __restrict__ rp1, int* __restrict__ rp2,
                         int* __restrict__ wc0, int* __restrict__ wc1, int* __restrict__ wc2) {
    int t = blockIdx.x * blockDim.x + threadIdx.x;
    const int nA = NT + 1, nB = NA + 1, nC = NT + 1;
    if (t < nA) rp0[t] = 0;
    else if (t < nA + nB) rp1[t - nA] = 0;
    else if (t < nA + nB + nC) rp2[t - nA - nB] = 0;
    else {
        int u = t - nA - nB - nC;
        if (u < NT) wc0[u] = 0;
        else if (u < NT + NA) wc1[u - NT] = 0;
        else if (u < NT + NA + NT) wc2[u - NT - NA] = 0;
    }
}

__global__ void count_all(const int* __restrict__ ei0, const int* __restrict__ ei1,
                          const int* __restrict__ ei2,
                          int* __restrict__ d0, int* __restrict__ d1, int* __restrict__ d2) {
    int t = blockIdx.x * blockDim.x + threadIdx.x;
    if (t < E_IN)                  atomicAdd(&d0[__ldg(ei0 + E_IN + t)], 1);
    else if (t < E_IN + E_OUT)     atomicAdd(&d1[__ldg(ei1 + E_OUT + (t - E_IN))], 1);
    else if (t < E_TOT)            atomicAdd(&d2[__ldg(ei2 + E_SP + (t - E_IN - E_OUT))], 1);
}

__global__ void scan1_all(int* __restrict__ d0, int* __restrict__ b0, int n0, int nb0,
                          int* __restrict__ d1, int* __restrict__ b1, int n1, int nb1,
                          int* __restrict__ d2, int* __restrict__ b2, int n2) {
    int* d; int* bs; int n; int lb;
    if (blockIdx.x < nb0)            { d = d0; bs = b0; n = n0; lb = blockIdx.x; }
    else if (blockIdx.x < nb0 + nb1) { d = d1; bs = b1; n = n1; lb = blockIdx.x - nb0; }
    else                             { d = d2; bs = b2; n = n2; lb = blockIdx.x - nb0 - nb1; }
    __shared__ int s[SCAN_B];
    int i = lb * SCAN_B + threadIdx.x;
    int v = (i < n) ? d[i] : 0;
    s[threadIdx.x] = v;
    __syncthreads();
    for (int o = 1; o < SCAN_B; o <<= 1) {
        int t = (threadIdx.x >= o) ? s[threadIdx.x - o] : 0;
        __syncthreads();
        s[threadIdx.x] += t;
        __syncthreads();
    }
    if (i < n) d[i] = s[threadIdx.x] - v;        // exclusive
    if (threadIdx.x == SCAN_B - 1) bs[lb] = s[SCAN_B - 1];
}

__global__ void scan2_all(int* __restrict__ b0, int nb0,
                          int* __restrict__ b1, int nb1,
                          int* __restrict__ b2, int nb2) {
    int* bs; int nb;
    if (blockIdx.x == 0)      { bs = b0; nb = nb0; }
    else if (blockIdx.x == 1) { bs = b1; nb = nb1; }
    else                      { bs = b2; nb = nb2; }
    __shared__ int s[SCAN_B];
    int v = (threadIdx.x < nb) ? bs[threadIdx.x] : 0;
    s[threadIdx.x] = v;
    __syncthreads();
    for (int o = 1; o < SCAN_B; o <<= 1) {
        int t = (threadIdx.x >= o) ? s[threadIdx.x - o] : 0;
        __syncthreads();
        s[threadIdx.x] += t;
        __syncthreads();
    }
    if (threadIdx.x < nb) bs[threadIdx.x] = s[threadIdx.x] - v;   // exclusive
}

__global__ void scan3_all(int* __restrict__ d0, const int* __restrict__ b0, int n0, int nb0,
                          int* __restrict__ d1, const int* __restrict__ b1, int n1, int nb1,
                          int* __restrict__ d2, const int* __restrict__ b2, int n2) {
    if (blockIdx.x == 0 && threadIdx.x == 0) {
        d0[n0] = E_IN; d1[n1] = E_OUT; d2[n2] = E_SP;
    }
    int* d; const int* bs; int n; int lb;
    if (blockIdx.x < nb0)            { d = d0; bs = b0; n = n0; lb = blockIdx.x; }
    else if (blockIdx.x < nb0 + nb1) { d = d1; bs = b1; n = n1; lb = blockIdx.x - nb0; }
    else                             { d = d2; bs = b2; n = n2; lb = blockIdx.x - nb0 - nb1; }
    int i = lb * SCAN_B + threadIdx.x;
    if (i < n) d[i] += bs[lb];
}

__global__ void fill_all(const int* __restrict__ ei0, const int* __restrict__ ei1,
                         const int* __restrict__ ei2,
                         const int* __restrict__ r0, const int* __restrict__ r1,
                         const int* __restrict__ r2,
                         int* __restrict__ w0, int* __restrict__ w1, int* __restrict__ w2,
                         int* __restrict__ a0, int* __restrict__ a1, int* __restrict__ a2) {
    int t = blockIdx.x * blockDim.x + threadIdx.x;
    const int* ei; const int* r; int* w; int* adj; int e, E;
    if (t < E_IN)              { ei = ei0; r = r0; w = w0; adj = a0; e = t;                 E = E_IN;  }
    else if (t < E_IN + E_OUT) { ei = ei1; r = r1; w = w1; adj = a1; e = t - E_IN;          E = E_OUT; }
    else if (t < E_TOT)        { ei = ei2; r = r2; w = w2; adj = a2; e = t - E_IN - E_OUT;  E = E_SP;  }
    else return;
    int si = __ldg(ei + e);
    int di = __ldg(ei + E + e);
    int pos = r[di] + atomicAdd(&w[di], 1);
    adj[pos] = si;
}

// ---------------- node kernels ----------------
__global__ void enc_kernel(const float* __restrict__ x, const float* __restrict__ W,
                           const float* __restrict__ b, float* __restrict__ out,
                           int n, int K) {
    extern __shared__ float Ws[];
    for (int i = threadIdx.x; i < K * 32; i += blockDim.x) Ws[i] = W[i];
    __syncthreads();
    int lane = threadIdx.x & 31;
    int warp = blockIdx.x * (blockDim.x >> 5) + (threadIdx.x >> 5);
    int nw = gridDim.x * (blockDim.x >> 5);
    float bl = b[lane];
    for (int node = warp; node < n; node += nw) {
        const float* xr = x + (size_t)node * K;
        float acc = bl;
        for (int k = 0; k < K; k++) acc = fmaf(xr[k], Ws[k * 32 + lane], acc);
        out[node * 32 + lane] = fmaxf(acc, 0.f);
    }
}

// tiled projection with 4-node register reuse
template <int NATT, bool STOREH>
__global__ void projT_kernel(const float* __restrict__ x, const float* __restrict__ W,
                             const float* __restrict__ b, __half* __restrict__ hout, int n,
                             const float* __restrict__ a0, float* __restrict__ o0,
                             const float* __restrict__ a1, float* __restrict__ o1,
                             const float* __restrict__ a2, float* __restrict__ o2,
                             const float* __restrict__ a3, float* __restrict__ o3) {
    __shared__ float Ws[32 * 32];
    __shared__ float Xs[128 * 33];
    int tid = threadIdx.x;
    for (int i = tid; i < 1024; i += blockDim.x) Ws[i] = W[i];
    int nl = tid >> 3;            // node-slot within 32 (0..31)
    int jq = (tid & 7) * 4;       // first output column of this thread's quad
    int head = (tid & 7) >> 1;    // head covered by this quad-pair
    float4 bq = *(const float4*)(b + jq);
    float4 av0 = make_float4(0,0,0,0), av1 = av0, av2 = av0, av3 = av0;
    if (NATT > 0) av0 = *(const float4*)(a0 + jq);
    if (NATT > 1) av1 = *(const float4*)(a1 + jq);
    if (NATT > 2) av2 = *(const float4*)(a2 + jq);
    if (NATT > 3) av3 = *(const float4*)(a3 + jq);
    __syncthreads();
    int ntiles = (n + 127) >> 7;
    for (int tile = blockIdx.x; tile < ntiles; tile += gridDim.x) {
        int base = tile * 128;
        #pragma unroll
        for (int r = 0; r < 4; r++) {
            int node = base + nl + r * 32;
            float4 xq = (node < n) ? *(const float4*)(x + (size_t)node * 32 + jq)
                                   : make_float4(0.f, 0.f, 0.f, 0.f);
            int row = nl + r * 32;
            Xs[row * 33 + jq + 0] = xq.x;
            Xs[row * 33 + jq + 1] = xq.y;
            Xs[row * 33 + jq + 2] = xq.z;
            Xs[row * 33 + jq + 3] = xq.w;
        }
        __syncthreads();
        float4 acc[4] = {bq, bq, bq, bq};
        #pragma unroll
        for (int k = 0; k < 32; k++) {
            float4 wk = *(const float4*)(Ws + k * 32 + jq);
            #pragma unroll
            for (int r = 0; r < 4; r++) {
                float xk = Xs[(nl + r * 32) * 33 + k];
                acc[r].x = fmaf(xk, wk.x, acc[r].x);
                acc[r].y = fmaf(xk, wk.y, acc[r].y);
                acc[r].z = fmaf(xk, wk.z, acc[r].z);
                acc[r].w = fmaf(xk, wk.w, acc[r].w);
            }
        }
        #pragma unroll
        for (int r = 0; r < 4; r++) {
            int node = base + nl + r * 32;
            bool valid = node < n;
            if (STOREH && valid) {
                __half2 p0 = __floats2half2_rn(acc[r].x, acc[r].y);
                __half2 p1 = __floats2half2_rn(acc[r].z, acc[r].w);
                __half2* hp = (__half2*)(hout + (size_t)node * 32 + jq);
                hp[0] = p0;
                hp[1] = p1;
            }
            #define DOTQ(av, ov) { \
                float p = acc[r].x*(av).x + acc[r].y*(av).y + acc[r].z*(av).z + acc[r].w*(av).w; \
                p += __shfl_xor_sync(0xffffffffu, p, 1); \
                if (valid && ((tid & 1) == 0)) (ov)[node * 4 + head] = p; }
            if (NATT > 0) DOTQ(av0, o0)
            if (NATT > 1) DOTQ(av1, o1)
            if (NATT > 2) DOTQ(av2, o2)
            if (NATT > 3) DOTQ(av3, o3)
            #undef DOTQ
        }
        __syncthreads();
    }
}

// ---------------- dual-edge half2 gather-aggregation ----------------
// Warp split into two 16-lane halves: sub=lane>>4 processes edges s+sub, s+sub+2, ...
// Each lane covers features (2*sl, 2*sl+1) via one __half2 load -> every warp
// instruction (adj/asrc/h LDG, exp, fma) serves TWO edges. Partial den/acc merged
// with shfl_xor(16) once per node. Returns merged float2 (all lanes identical).
__device__ __forceinline__ float2 gather_rel2(const int* __restrict__ rp,
                                              const int* __restrict__ adj,
                                              const float* __restrict__ asrc,
                                              const float* __restrict__ adst,
                                              const __half* __restrict__ h,
                                              int node, int sub, int sl, int head) {
    float ad = __ldg(adst + node * 4 + head);
    int s = __ldg(rp + node), e = __ldg(rp + node + 1);
    float den = 0.f, ax = 0.f, ay = 0.f;
    for (int i = s + sub; i < e; i += 4) {
        int a0 = __ldg(adj + i);
        bool h2 = (i + 2 < e);
        int a1 = h2 ? __ldg(adj + i + 2) : a0;
        float sa0 = __ldg(asrc + a0 * 4 + head);
        float sa1 = __ldg(asrc + a1 * 4 + head);
        __half2 q0 = __ldg((const __half2*)(h + (size_t)a0 * 32) + sl);
        __half2 q1 = __ldg((const __half2*)(h + (size_t)a1 * 32) + sl);
        float v0 = sa0 + ad; if (v0 < 0.f) v0 *= 0.2f;
        float e0 = __expf(v0);
        float2 f0 = __half22float2(q0);
        den += e0;
        ax = fmaf(e0, f0.x, ax);
        ay = fmaf(e0, f0.y, ay);
        if (h2) {
            float v1 = sa1 + ad; if (v1 < 0.f) v1 *= 0.2f;
            float e1 = __expf(v1);
            float2 f1 = __half22float2(q1);
            den += e1;
            ax = fmaf(e1, f1.x, ax);
            ay = fmaf(e1, f1.y, ay);
        }
    }
    den += __shfl_xor_sync(0xffffffffu, den, 16);
    ax  += __shfl_xor_sync(0xffffffffu, ax, 16);
    ay  += __shfl_xor_sync(0xffffffffu, ay, 16);
    float inv = 1.f / (den + 1e-16f);
    return make_float2(fmaxf(ax * inv, 0.f), fmaxf(ay * inv, 0.f));
}

__global__ void agg_kernel(const int* __restrict__ rp0, const int* __restrict__ adj0,
                           const int* __restrict__ rp2, const int* __restrict__ adj2,
                           const int* __restrict__ rp1, const int* __restrict__ adj1,
                           const float* __restrict__ asrc0, const float* __restrict__ adst0,
                           const float* __restrict__ asrc2, const float* __restrict__ adst2,
                           const float* __restrict__ asrc1, const float* __restrict__ adst1,
                           const __half* __restrict__ ha, const __half* __restrict__ ht,
                           float* __restrict__ o0out, float* __restrict__ o2out,
                           float* __restrict__ xa,
                           const float* __restrict__ lng, const float* __restrict__ lnb) {
    int lane = threadIdx.x & 31;
    int warp = blockIdx.x * (blockDim.x >> 5) + (threadIdx.x >> 5);
    int nw = gridDim.x * (blockDim.x >> 5);
    int sub = lane >> 4;           // half-warp id
    int sl = lane & 15;            // sub-lane: features 2*sl, 2*sl+1
    int head = sl >> 2;            // head of this feature pair
    float gl = lng[lane], bl = lnb[lane];
    for (int idx = warp; idx < NT + NA; idx += nw) {
        if (idx < NT) {
            int node = idx;
            float2 x0 = gather_rel2(rp0, adj0, asrc0, adst0, ha, node, sub, sl, head);
            float2 x2 = gather_rel2(rp2, adj2, asrc2, adst2, ht, node, sub, sl, head);
            if (lane < 16) {
                *(float2*)(o0out + (size_t)node * 32 + 2 * sl) = x0;
                *(float2*)(o2out + (size_t)node * 32 + 2 * sl) = x2;
            }
        } else {
            int node = idx - NT;
            float2 ov = gather_rel2(rp1, adj1, asrc1, adst1, ht, node, sub, sl, head);
            // expand pair layout to per-lane feature layout
            float fx = __shfl_sync(0xffffffffu, ov.x, lane >> 1);
            float fy = __shfl_sync(0xffffffffu, ov.y, lane >> 1);
            float o = (lane & 1) ? fy : fx;
            int i = node * 32 + lane;
            float v = o + xa[i];        // relation-group softmax weight is exactly 1
            float m = wsum32(v) * (1.f / 32.f);
            float c = v - m;
            float var = wsum32(c * c) * (1.f / 32.f);
            xa[i] = c * rsqrtf(var + 1e-5f) * gl + bl;
        }
    }
}

// addr-only aggregation for the last layer (tx path is dead code)
__global__ void agg_addr_kernel(const int* __restrict__ rp1, const int* __restrict__ adj1,
                                const float* __restrict__ asrc1, const float* __restrict__ adst1,
                                const __half* __restrict__ ht, float* __restrict__ xa,
                                const float* __restrict__ lng, const float* __restrict__ lnb) {
    int lane = threadIdx.x & 31;
    int warp = blockIdx.x * (blockDim.x >> 5) + (threadIdx.x >> 5);
    int nw = gridDim.x * (blockDim.x >> 5);
    int sub = lane >> 4;
    int sl = lane & 15;
    int head = sl >> 2;
    float gl = lng[lane], bl = lnb[lane];
    for (int node = warp; node < NA; node += nw) {
        float2 ov = gather_rel2(rp1, adj1, asrc1, adst1, ht, node, sub, sl, head);
        float fx = __shfl_sync(0xffffffffu, ov.x, lane >> 1);
        float fy = __shfl_sync(0xffffffffu, ov.y, lane >> 1);
        float o = (lane & 1) ? fy : fx;
        int i = node * 32 + lane;
        float v = o + xa[i];
        float m = wsum32(v) * (1.f / 32.f);
        float c = v - m;
        float var = wsum32(c * c) * (1.f / 32.f);
        xa[i] = c * rsqrtf(var + 1e-5f) * gl + bl;
    }
}

// tiled semantic-attention score with 4-node register reuse
__global__ void scoreT_kernel(const float* __restrict__ o0, const float* __restrict__ o2,
                              const float* __restrict__ kw, const float* __restrict__ kb,
                              float* __restrict__ sacc, int n) {
    __shared__ float Ws[32 * 32];
    __shared__ float X0[128 * 33];
    __shared__ float X2[128 * 33];
    __shared__ float s0[32], s2[32];
    int tid = threadIdx.x;
    for (int i = tid; i < 1024; i += blockDim.x) Ws[i] = kw[i];
    int nl = tid >> 3;
    int jq = (tid & 7) * 4;
    float4 kbq = *(const float4*)(kb + jq);
    float4 t0 = make_float4(0,0,0,0), t2 = make_float4(0,0,0,0);
    __syncthreads();
    int ntiles = (n + 127) >> 7;
    for (int tile = blockIdx.x; tile < ntiles; tile += gridDim.x) {
        int base = tile * 128;
        #pragma unroll
        for (int r = 0; r < 4; r++) {
            int node = base + nl + r * 32;
            float4 q0 = (node < n) ? *(const float4*)(o0 + (size_t)node * 32 + jq) : make_float4(0,0,0,0);
            float4 q2 = (node < n) ? *(const float4*)(o2 + (size_t)node * 32 + jq) : make_float4(0,0,0,0);
            int row = nl + r * 32;
            X0[row*33+jq+0]=q0.x; X0[row*33+jq+1]=q0.y; X0[row*33+jq+2]=q0.z; X0[row*33+jq+3]=q0.w;
            X2[row*33+jq+0]=q2.x; X2[row*33+jq+1]=q2.y; X2[row*33+jq+2]=q2.z; X2[row*33+jq+3]=q2.w;
        }
        __syncthreads();
        float4 a0[4] = {kbq, kbq, kbq, kbq};
        float4 a2[4] = {kbq, kbq, kbq, kbq};
        #pragma unroll
        for (int k = 0; k < 32; k++) {
            float4 wk = *(const float4*)(Ws + k * 32 + jq);
            #pragma unroll
            for (int r = 0; r < 4; r++) {
                float x0k = X0[(nl + r * 32) * 33 + k];
                float x2k = X2[(nl + r * 32) * 33 + k];
                a0[r].x = fmaf(x0k, wk.x, a0[r].x); a0[r].y = fmaf(x0k, wk.y, a0[r].y);
                a0[r].z = fmaf(x0k, wk.z, a0[r].z); a0[r].w = fmaf(x0k, wk.w, a0[r].w);
                a2[r].x = fmaf(x2k, wk.x, a2[r].x); a2[r].y = fmaf(x2k, wk.y, a2[r].y);
                a2[r].z = fmaf(x2k, wk.z, a2[r].z); a2[r].w = fmaf(x2k, wk.w, a2[r].w);
            }
        }
        #pragma unroll
        for (int r = 0; r < 4; r++) {
            int node = base + nl + r * 32;
            if (node < n) {
                t0.x += tanhf(a0[r].x); t0.y += tanhf(a0[r].y);
                t0.z += tanhf(a0[r].z); t0.w += tanhf(a0[r].w);
                t2.x += tanhf(a2[r].x); t2.y += tanhf(a2[r].y);
                t2.z += tanhf(a2[r].z); t2.w += tanhf(a2[r].w);
            }
        }
        __syncthreads();
    }
    if (tid < 32) { s0[tid] = 0.f; s2[tid] = 0.f; }
    __syncthreads();
    atomicAdd(&s0[jq+0], t0.x); atomicAdd(&s0[jq+1], t0.y);
    atomicAdd(&s0[jq+2], t0.z); atomicAdd(&s0[jq+3], t0.w);
    atomicAdd(&s2[jq+0], t2.x); atomicAdd(&s2[jq+1], t2.y);
    atomicAdd(&s2[jq+2], t2.z); atomicAdd(&s2[jq+3], t2.w);
    __syncthreads();
    if (tid < 32) {
        atomicAdd(&sacc[tid * 32], s0[tid]);
        atomicAdd(&sacc[1024 + tid * 32], s2[tid]);
    }
}

// softmax over the 2 tx-relation scores
__global__ void score_fin(const float* __restrict__ acc0, const float* __restrict__ acc2,
                          const float* __restrict__ q, float* __restrict__ attn, float invN) {
    int j = threadIdx.x;  // 32 threads
    float s0 = q[j] * acc0[j * 32] * invN;
    float s2 = q[j] * acc2[j * 32] * invN;
    s0 = wsum32(s0);
    s2 = wsum32(s2);
    if (j == 0) {
        float m = fmaxf(s0, s2);
        float e0 = __expf(s0 - m), e2 = __expf(s2 - m);
        float inv = 1.f / (e0 + e2);
        attn[0] = e0 * inv;
        attn[1] = e2 * inv;
    }
}

__global__ void upd_tx_kernel(const float* __restrict__ o0, const float* __restrict__ o2,
                              const float* __restrict__ attn, float* __restrict__ xt,
                              const float* __restrict__ g, const float* __restrict__ b, int n) {
    int lane = threadIdx.x & 31;
    int node = blockIdx.x * (blockDim.x >> 5) + (threadIdx.x >> 5);
    if (node >= n) return;
    float a0 = attn[0], a2 = attn[1];
    int i = node * 32 + lane;
    float v = fmaxf(a0 * o0[i] + a2 * o2[i], 0.f) + xt[i];
    float m = wsum32(v) * (1.f / 32.f);
    float c = v - m;
    float var = wsum32(c * c) * (1.f / 32.f);
    xt[i] = c * rsqrtf(var + 1e-5f) * g[lane] + b[lane];
}

__global__ void head_kernel(const float* __restrict__ xa, const float* __restrict__ w,
                            const float* __restrict__ b, float* __restrict__ out, int n) {
    int lane = threadIdx.x & 31;
    int node = blockIdx.x * (blockDim.x >> 5) + (threadIdx.x >> 5);
    if (node >= n) return;
    float v = xa[node * 32 + lane];
    float s0 = wsum32(v * w[lane * 2 + 0]);
    float s1 = wsum32(v * w[lane * 2 + 1]);
    if (lane == 0) {
        out[node * 2 + 0] = s0 + b[0];
        out[node * 2 + 1] = s1 + b[1];
    }
}

// ---------------- launch ----------------
extern "C" void kernel_launch(void* const* d_in, const int* in_sizes, int n_in,
                              void* d_out, int out_size) {
    const float* x_addr  = (const float*)d_in[0];
    const float* x_tx    = (const float*)d_in[1];
    const int*   ei_in   = (const int*)d_in[2];
    const int*   ei_out  = (const int*)d_in[3];
    const int*   ei_sp   = (const int*)d_in[4];
    const float* enc_w_a = (const float*)d_in[5];
    const float* enc_b_a = (const float*)d_in[6];
    const float* enc_w_t = (const float*)d_in[7];
    const float* enc_b_t = (const float*)d_in[8];
    const float* ln_a_g  = (const float*)d_in[9];
    const float* ln_a_b  = (const float*)d_in[10];
    const float* ln_t_g  = (const float*)d_in[11];
    const float* ln_t_b  = (const float*)d_in[12];
    const float* pw_a    = (const float*)d_in[13];
    const float* pb_a    = (const float*)d_in[14];
    const float* pw_t    = (const float*)d_in[15];
    const float* pb_t    = (const float*)d_in[16];
    const float* att_src = (const float*)d_in[17];
    const float* att_dst = (const float*)d_in[18];
    const float* klin_w  = (const float*)d_in[19];
    const float* klin_b  = (const float*)d_in[20];
    const float* qv      = (const float*)d_in[21];
    const float* lin_w   = (const float*)d_in[22];
    const float* lin_b   = (const float*)d_in[23];
    float* out = (float*)d_out;

    float *xa, *xt;
    __half *ha, *ht;
    float *asrc0, *adst0, *asrc1, *adst1, *asrc2, *adst2;
    float *o0, *o2, *sacc, *attn;
    int *rp0, *rp1, *rp2, *wc0, *wc1, *wc2, *adj0, *adj1, *adj2, *bs0, *bs1, *bs2;
    cudaGetSymbolAddress((void**)&xa, g_xa);
    cudaGetSymbolAddress((void**)&xt, g_xt);
    cudaGetSymbolAddress((void**)&ha, g_ha);
    cudaGetSymbolAddress((void**)&ht, g_ht);
    cudaGetSymbolAddress((void**)&asrc0, g_asrc0);
    cudaGetSymbolAddress((void**)&adst0, g_adst0);
    cudaGetSymbolAddress((void**)&asrc1, g_asrc1);
    cudaGetSymbolAddress((void**)&adst1, g_adst1);
    cudaGetSymbolAddress((void**)&asrc2, g_asrc2);
    cudaGetSymbolAddress((void**)&adst2, g_adst2);
    cudaGetSymbolAddress((void**)&o0, g_o0);
    cudaGetSymbolAddress((void**)&o2, g_o2);
    cudaGetSymbolAddress((void**)&sacc, g_sacc);
    cudaGetSymbolAddress((void**)&attn, g_attn);
    cudaGetSymbolAddress((void**)&rp0, g_rp0);
    cudaGetSymbolAddress((void**)&rp1, g_rp1);
    cudaGetSymbolAddress((void**)&rp2, g_rp2);
    cudaGetSymbolAddress((void**)&wc0, g_wcur0);
    cudaGetSymbolAddress((void**)&wc1, g_wcur1);
    cudaGetSymbolAddress((void**)&wc2, g_wcur2);
    cudaGetSymbolAddress((void**)&adj0, g_adj0);
    cudaGetSymbolAddress((void**)&adj1, g_adj1);
    cudaGetSymbolAddress((void**)&adj2, g_adj2);
    cudaGetSymbolAddress((void**)&bs0, g_bsums0);
    cudaGetSymbolAddress((void**)&bs1, g_bsums1);
    cudaGetSymbolAddress((void**)&bs2, g_bsums2);

    const int WPB = 8;
    const int TPB = WPB * 32;        // 256 threads
    dim3 gridA((NA + WPB - 1) / WPB), gridT((NT + WPB - 1) / WPB), blk(TPB);
    const int PGRID = 1184;          // persistent grid (agg)
    const int TGRID = 1480;          // tiled-GEMM grid (proj/score)

    // ---- CSR build (graph static across layers) ----
    const int ZTOT = (NT + 1) + (NA + 1) + (NT + 1) + NT + NA + NT;
    zero_csr<<<(ZTOT + 255) / 256, 256>>>(rp0, rp1, rp2, wc0, wc1, wc2);
    count_all<<<(E_TOT + 255) / 256, 256>>>(ei_in, ei_out, ei_sp, rp0, rp1, rp2);
    int nbT = (NT + SCAN_B - 1) / SCAN_B;
    int nbA = (NA + SCAN_B - 1) / SCAN_B;
    scan1_all<<<nbT + nbA + nbT, SCAN_B>>>(rp0, bs0, NT, nbT, rp1, bs1, NA, nbA, rp2, bs2, NT);
    scan2_all<<<3, SCAN_B>>>(bs0, nbT, bs1, nbA, bs2, nbT);
    scan3_all<<<nbT + nbA + nbT, SCAN_B>>>(rp0, bs0, NT, nbT, rp1, bs1, NA, nbA, rp2, bs2, NT);
    fill_all<<<(E_TOT + 255) / 256, 256>>>(ei_in, ei_out, ei_sp, rp0, rp1, rp2,
                                           wc0, wc1, wc2, adj0, adj1, adj2);

    // ---- encoders ----
    enc_kernel<<<TGRID, TPB, 53 * 32 * 4>>>(x_addr, enc_w_a, enc_b_a, xa, NA, 53);
    enc_kernel<<<TGRID, TPB, 6 * 32 * 4>>>(x_tx, enc_w_t, enc_b_t, xt, NT, 6);

    // ---- layers 1..3 (full) ----
    for (int l = 0; l < NLAYERS - 1; l++) {
        const float* PWA = pw_a + l * 32 * 32;
        const float* PBA = pb_a + l * 32;
        const float* PWT = pw_t + l * 32 * 32;
        const float* PBT = pb_t + l * 32;
        const float* AS = att_src + l * 3 * 32;  // [3][32]
        const float* AD = att_dst + l * 3 * 32;
        const float* KW = klin_w + l * 32 * 32;
        const float* KB = klin_b + l * 32;
        const float* Q  = qv + l * 32;

        projT_kernel<2, true><<<TGRID, blk>>>(xa, PWA, PBA, ha, NA,
                                              AS + 0 * 32, asrc0,   // rel0 src = addr
                                              AD + 1 * 32, adst1,   // rel1 dst = addr
                                              nullptr, nullptr, nullptr, nullptr);
        projT_kernel<4, true><<<TGRID, blk>>>(xt, PWT, PBT, ht, NT,
                                              AD + 0 * 32, adst0,   // rel0 dst = tx
                                              AS + 1 * 32, asrc1,   // rel1 src = tx
                                              AS + 2 * 32, asrc2,   // rel2 src = tx
                                              AD + 2 * 32, adst2);

        cudaMemsetAsync(sacc, 0, 2 * 32 * 32 * sizeof(float));

        agg_kernel<<<PGRID, blk>>>(rp0, adj0, rp2, adj2, rp1, adj1,
                                   asrc0, adst0, asrc2, adst2, asrc1, adst1,
                                   ha, ht, o0, o2, xa, ln_a_g, ln_a_b);
        scoreT_kernel<<<TGRID, blk>>>(o0, o2, KW, KB, sacc, NT);
        score_fin<<<1, 32>>>(sacc, sacc + 1024, Q, attn, 1.0f / (float)NT);
        upd_tx_kernel<<<gridT, blk>>>(o0, o2, attn, xt, ln_t_g, ln_t_b, NT);
    }

    // ---- layer 4: tx output is dead (only xa reaches the head) ----
    {
        const int l = NLAYERS - 1;
        const float* PWA = pw_a + l * 32 * 32;
        const float* PBA = pb_a + l * 32;
        const float* PWT = pw_t + l * 32 * 32;
        const float* PBT = pb_t + l * 32;
        const float* AS = att_src + l * 3 * 32;
        const float* AD = att_dst + l * 3 * 32;

        // addr projection: only adst1 needed, h is dead
        projT_kernel<1, false><<<TGRID, blk>>>(xa, PWA, PBA, ha, NA,
                                               AD + 1 * 32, adst1,
                                               nullptr, nullptr, nullptr, nullptr,
                                               nullptr, nullptr);
        // tx projection: ht + asrc1 needed only
        projT_kernel<1, true><<<TGRID, blk>>>(xt, PWT, PBT, ht, NT,
                                              AS + 1 * 32, asrc1,
                                              nullptr, nullptr, nullptr, nullptr,
                                              nullptr, nullptr);
        agg_addr_kernel<<<PGRID, blk>>>(rp1, adj1, asrc1, adst1, ht, xa, ln_a_g, ln_a_b);
    }

    head_kernel<<<gridA, blk>>>(xa, lin_w, lin_b, out, NA);
}